// round 7
// baseline (speedup 1.0000x reference)
#include <cuda_runtime.h>
#include <cuda_bf16.h>
#include <cstdint>

#define EPS_F      1e-8f
#define EPS4_F     4e-8f                 // 4*EPS  (clip on raw squares)
#define EPS16_F    1.6e-7f               // 16*EPS (clip on z product)
#define EPS64_F    6.4e-7f               // 64*EPS (clip on raw det)
#define TAU4_INV   13.333333333333334f   // 4/0.3 (cube-root 1/64 folded in)
#define LOG2E_F    1.4426950408889634f

static constexpr int NT  = 256;
static constexpr int NB1 = 4096;         // 4096*256 = 1,048,576 threads = 1 box/thread

__device__ float2       g_partials[NB1];
__device__ unsigned int g_done_count;

__device__ __forceinline__ float warp_sum(float v) {
    #pragma unroll
    for (int off = 16; off > 0; off >>= 1)
        v += __shfl_xor_sync(0xFFFFFFFFu, v, off);
    return v;
}
__device__ __forceinline__ float fsqrt_ap(float x) {
    float r; asm("sqrt.approx.f32 %0, %1;" : "=f"(r) : "f"(x)); return r;
}
__device__ __forceinline__ float ex2_ap(float x) {
    float r; asm("ex2.approx.f32 %0, %1;" : "=f"(r) : "f"(x)); return r;
}
__device__ __forceinline__ float lg2_ap(float x) {
    float r; asm("lg2.approx.f32 %0, %1;" : "=f"(r) : "f"(x)); return r;
}

__global__ __launch_bounds__(NT) void gwd_fused(
    const float* __restrict__ pred,
    const float* __restrict__ gt,
    float* __restrict__ out,
    int total)
{
    float lsum = 0.0f;
    float msum = 0.0f;

    // one box per thread (grid-stride loop runs once for this shape)
    for (int i = blockIdx.x * NT + threadIdx.x; i < total; i += gridDim.x * NT) {
        const float* p = pred + 7ll * i;
        const float* g = gt   + 7ll * i;

        // 14 independent scalar loads batched up front (R1-proven pattern)
        float p0 = __ldg(p + 0), p1 = __ldg(p + 1), p2 = __ldg(p + 2);
        float p3 = __ldg(p + 3), p4v = __ldg(p + 4), p5 = __ldg(p + 5);
        float p6 = __ldg(p + 6);
        float g0 = __ldg(g + 0), g1 = __ldg(g + 1), g2 = __ldg(g + 2);
        float g3 = __ldg(g + 3), g4v = __ldg(g + 4), g5 = __ldg(g + 5);
        float g6 = __ldg(g + 6);

        // mean distance
        float dx = p0 - g0, dy = p1 - g1, dz = p2 - g2;
        float mu = fmaf(dx, dx, fmaf(dy, dy, dz * dz));

        // raw squared extents (covariance eigvals = these * 0.25, folded out)
        float tp = p3 * p3, up = p4v * p4v, vp = p5 * p5;
        float tt = g3 * g3, ut = g4v * g4v, vt = g5 * g5;

        float mtp = fmaxf(tp, EPS4_F);
        float mup = fmaxf(up, EPS4_F);
        float mvp = fmaxf(vp, EPS4_F);

        // 2x2 xy block of M = sqrt(Sp) St sqrt(Sp) (raw units)
        float cd = __cosf(p6 - g6);
        float cc = cd * cd;
        float ss = 1.0f - cc;
        float t1 = mtp * tt, t2 = mup * ut;
        float t3 = mtp * ut, t4 = mup * tt;
        float trM = fmaf(cc, t1 + t2, ss * (t3 + t4));
        // sqrt(l1)+sqrt(l2) = sqrt(trM + 2*sqrt(detM)), detM = t1*t2 (M PSD)
        float trS = fsqrt_ap(fmaf(2.0f, fsqrt_ap(t1 * t2), trM));

        // z block
        float sz = fsqrt_ap(fmaxf(mvp * vt, EPS16_F));

        float traces = (tp + up + vp) + (tt + ut + vt);
        float w2 = fmaf(0.25f, traces - 2.0f * (trS + sz), mu);

        // det(sigma_t)^(-1/3) / TAU, with the 1/64 det factor folded into TAU4_INV
        float detr = fmaxf(tt * ut * vt, EPS64_F);
        float invd = ex2_ap(lg2_ap(detr) * (-1.0f / 3.0f)) * TAU4_INV;

        float loss = 1.0f - ex2_ap(-w2 * invd * LOG2E_F);
        if (g0 != 0.0f) { lsum += loss; msum += 1.0f; }
    }

    // block reduction
    lsum = warp_sum(lsum);
    msum = warp_sum(msum);

    __shared__ float sl[NT / 32];
    __shared__ float sm[NT / 32];
    int lane = threadIdx.x & 31;
    int wid  = threadIdx.x >> 5;
    if (lane == 0) { sl[wid] = lsum; sm[wid] = msum; }
    __syncthreads();

    __shared__ bool is_last;
    if (threadIdx.x == 0) {
        float vl = 0.0f, vm = 0.0f;
        #pragma unroll
        for (int w = 0; w < NT / 32; w++) { vl += sl[w]; vm += sm[w]; }
        g_partials[blockIdx.x] = make_float2(vl, vm);
        __threadfence();
        unsigned int ticket = atomicAdd(&g_done_count, 1u);
        is_last = (ticket == (unsigned)(gridDim.x - 1));
    }
    __syncthreads();

    // last block finalizes (deterministic order); chip is still hot
    if (is_last) {
        double l = 0.0, m = 0.0;
        for (int i = threadIdx.x; i < NB1; i += NT) {
            float2 v = g_partials[i];
            l += (double)v.x;
            m += (double)v.y;
        }
        #pragma unroll
        for (int off = 16; off > 0; off >>= 1) {
            l += __shfl_xor_sync(0xFFFFFFFFu, l, off);
            m += __shfl_xor_sync(0xFFFFFFFFu, m, off);
        }
        __shared__ double dl[NT / 32];
        __shared__ double dm[NT / 32];
        if (lane == 0) { dl[wid] = l; dm[wid] = m; }
        __syncthreads();
        if (threadIdx.x == 0) {
            double vl = 0.0, vm = 0.0;
            #pragma unroll
            for (int w = 0; w < NT / 32; w++) { vl += dl[w]; vm += dm[w]; }
            out[0] = (float)(vl / (vm + (double)EPS_F));
            g_done_count = 0;   // reset for next graph replay
        }
    }
}

extern "C" void kernel_launch(void* const* d_in, const int* in_sizes, int n_in,
                              void* d_out, int out_size)
{
    const float* pred = (const float*)d_in[0];
    const float* gt   = (const float*)d_in[1];
    float* out = (float*)d_out;

    int total = in_sizes[0] / 7;

    gwd_fused<<<NB1, NT>>>(pred, gt, out, total);
}

// round 8
// speedup vs baseline: 1.0949x; 1.0949x over previous
#include <cuda_runtime.h>
#include <cuda_bf16.h>
#include <cstdint>

#define EPS_F      1e-8f
#define EPS4_F     4e-8f                 // 4*EPS  (clip on raw squares)
#define EPS16_F    1.6e-7f               // 16*EPS (clip on z product)
#define EPS64_F    6.4e-7f               // 64*EPS (clip on raw det)
#define TAU4_INV   13.333333333333334f   // 4/0.3 (cube-root 1/64 folded in)
#define LOG2E_F    1.4426950408889634f

static constexpr int NT   = 256;
static constexpr int NB1  = 1036;               // 148 SMs * 7 (smem-limited)
static constexpr int TILE_BOXES = 256;
static constexpr int TILE_F     = TILE_BOXES * 7;      // 1792 floats
static constexpr int TILE_BYTES = TILE_F * 4;          // 7168 B (mult of 16)

__device__ float2       g_partials[NB1];
__device__ unsigned int g_done_count;

__device__ __forceinline__ float warp_sum(float v) {
    #pragma unroll
    for (int off = 16; off > 0; off >>= 1)
        v += __shfl_xor_sync(0xFFFFFFFFu, v, off);
    return v;
}
__device__ __forceinline__ float fsqrt_ap(float x) {
    float r; asm("sqrt.approx.f32 %0, %1;" : "=f"(r) : "f"(x)); return r;
}
__device__ __forceinline__ float ex2_ap(float x) {
    float r; asm("ex2.approx.f32 %0, %1;" : "=f"(r) : "f"(x)); return r;
}
__device__ __forceinline__ float lg2_ap(float x) {
    float r; asm("lg2.approx.f32 %0, %1;" : "=f"(r) : "f"(x)); return r;
}
__device__ __forceinline__ uint32_t smem_u32(const void* p) {
    return (uint32_t)__cvta_generic_to_shared(p);
}
__device__ __forceinline__ void mbar_init(uint32_t mbar, uint32_t cnt) {
    asm volatile("mbarrier.init.shared.b64 [%0], %1;" :: "r"(mbar), "r"(cnt) : "memory");
}
__device__ __forceinline__ void mbar_expect_tx(uint32_t mbar, uint32_t bytes) {
    asm volatile("mbarrier.arrive.expect_tx.shared::cta.b64 _, [%0], %1;"
                 :: "r"(mbar), "r"(bytes) : "memory");
}
__device__ __forceinline__ void mbar_wait(uint32_t mbar, uint32_t parity) {
    asm volatile(
        "{\n\t"
        ".reg .pred P;\n\t"
        "W_%=:\n\t"
        "mbarrier.try_wait.parity.acquire.cta.shared::cta.b64 P, [%0], %1, 0x989680;\n\t"
        "@P bra D_%=;\n\t"
        "bra W_%=;\n\t"
        "D_%=:\n\t"
        "}"
        :: "r"(mbar), "r"(parity) : "memory");
}
__device__ __forceinline__ void bulk_copy_g2s(uint32_t dst, const void* src,
                                              uint32_t bytes, uint32_t mbar) {
    asm volatile(
        "cp.async.bulk.shared::cta.global.mbarrier::complete_tx::bytes [%0], [%1], %2, [%3];"
        :: "r"(dst), "l"(src), "r"(bytes), "r"(mbar) : "memory");
}

// per-box loss; covariance factor 0.25 folded out algebraically
__device__ __forceinline__ void box_loss(
    const float* __restrict__ p, const float* __restrict__ g,
    float& lsum, float& msum)
{
    float p0 = p[0], p1 = p[1], p2 = p[2], p3 = p[3], p4v = p[4], p5 = p[5], p6 = p[6];
    float g0 = g[0], g1 = g[1], g2 = g[2], g3 = g[3], g4v = g[4], g5 = g[5], g6 = g[6];

    float dx = p0 - g0, dy = p1 - g1, dz = p2 - g2;
    float mu = fmaf(dx, dx, fmaf(dy, dy, dz * dz));

    float tp = p3 * p3, up = p4v * p4v, vp = p5 * p5;
    float tt = g3 * g3, ut = g4v * g4v, vt = g5 * g5;

    float mtp = fmaxf(tp, EPS4_F);
    float mup = fmaxf(up, EPS4_F);
    float mvp = fmaxf(vp, EPS4_F);

    float cd = __cosf(p6 - g6);
    float cc = cd * cd;
    float ss = 1.0f - cc;
    float t1 = mtp * tt, t2 = mup * ut;
    float t3 = mtp * ut, t4 = mup * tt;
    float trM = fmaf(cc, t1 + t2, ss * (t3 + t4));
    float trS = fsqrt_ap(fmaf(2.0f, fsqrt_ap(t1 * t2), trM));   // sqrt(l1)+sqrt(l2)

    float sz = fsqrt_ap(fmaxf(mvp * vt, EPS16_F));

    float traces = (tp + up + vp) + (tt + ut + vt);
    float w2 = fmaf(0.25f, traces - 2.0f * (trS + sz), mu);

    float detr = fmaxf(tt * ut * vt, EPS64_F);
    float invd = ex2_ap(lg2_ap(detr) * (-1.0f / 3.0f)) * TAU4_INV;

    float loss = 1.0f - ex2_ap(-w2 * invd * LOG2E_F);
    if (g0 != 0.0f) { lsum += loss; msum += 1.0f; }
}

__global__ __launch_bounds__(NT) void gwd_fused(
    const float* __restrict__ pred,
    const float* __restrict__ gt,
    float* __restrict__ out,
    int total)
{
    // double-buffered tiles: [buf][pred|gt]
    __shared__ __align__(16) float sp[2][TILE_F];
    __shared__ __align__(16) float sg[2][TILE_F];
    __shared__ __align__(8)  unsigned long long mbar_s[2];

    const uint32_t mbar0 = smem_u32(&mbar_s[0]);
    const uint32_t mbar1 = smem_u32(&mbar_s[1]);

    const int ntiles_full = total / TILE_BOXES;        // bulk-copied tiles

    if (threadIdx.x == 0) {
        mbar_init(mbar0, 1);
        mbar_init(mbar1, 1);
    }
    __syncthreads();

    float lsum = 0.0f;
    float msum = 0.0f;

    // local tile j -> global tile = blockIdx.x + j*gridDim.x
    const int t0 = blockIdx.x;
    const int stride = gridDim.x;

    // prologue: fill both buffers
    if (threadIdx.x == 0) {
        if (t0 < ntiles_full) {
            mbar_expect_tx(mbar0, 2 * TILE_BYTES);
            bulk_copy_g2s(smem_u32(sp[0]), pred + (long long)t0 * TILE_F, TILE_BYTES, mbar0);
            bulk_copy_g2s(smem_u32(sg[0]), gt   + (long long)t0 * TILE_F, TILE_BYTES, mbar0);
        }
        if (t0 + stride < ntiles_full) {
            mbar_expect_tx(mbar1, 2 * TILE_BYTES);
            bulk_copy_g2s(smem_u32(sp[1]), pred + (long long)(t0 + stride) * TILE_F, TILE_BYTES, mbar1);
            bulk_copy_g2s(smem_u32(sg[1]), gt   + (long long)(t0 + stride) * TILE_F, TILE_BYTES, mbar1);
        }
    }

    for (int j = 0; t0 + j * stride < ntiles_full; j++) {
        const int buf    = j & 1;
        const uint32_t parity = (j >> 1) & 1;
        mbar_wait(buf ? mbar1 : mbar0, parity);

        // stride-7 smem reads: gcd(7,32)=1 -> conflict-free
        box_loss(sp[buf] + 7 * threadIdx.x, sg[buf] + 7 * threadIdx.x, lsum, msum);

        __syncthreads();   // whole block done reading this buffer

        const int tnext = t0 + (j + 2) * stride;
        if (threadIdx.x == 0 && tnext < ntiles_full) {
            const uint32_t mb = buf ? mbar1 : mbar0;
            mbar_expect_tx(mb, 2 * TILE_BYTES);
            bulk_copy_g2s(smem_u32(sp[buf]), pred + (long long)tnext * TILE_F, TILE_BYTES, mb);
            bulk_copy_g2s(smem_u32(sg[buf]), gt   + (long long)tnext * TILE_F, TILE_BYTES, mb);
        }
    }

    // ragged tail boxes (0 for this shape): direct global loads, block 0
    const int tail0 = ntiles_full * TILE_BOXES;
    if (blockIdx.x == 0) {
        for (int b = tail0 + threadIdx.x; b < total; b += NT) {
            const float* p = pred + 7ll * b;
            const float* g = gt   + 7ll * b;
            float pr[7], gr[7];
            #pragma unroll
            for (int k = 0; k < 7; k++) { pr[k] = __ldg(p + k); gr[k] = __ldg(g + k); }
            box_loss(pr, gr, lsum, msum);
        }
    }

    // block reduction
    lsum = warp_sum(lsum);
    msum = warp_sum(msum);

    __shared__ float sl[NT / 32];
    __shared__ float sm[NT / 32];
    int lane = threadIdx.x & 31;
    int wid  = threadIdx.x >> 5;
    if (lane == 0) { sl[wid] = lsum; sm[wid] = msum; }
    __syncthreads();

    __shared__ bool is_last;
    if (threadIdx.x == 0) {
        float vl = 0.0f, vm = 0.0f;
        #pragma unroll
        for (int w = 0; w < NT / 32; w++) { vl += sl[w]; vm += sm[w]; }
        g_partials[blockIdx.x] = make_float2(vl, vm);
        __threadfence();
        unsigned int ticket = atomicAdd(&g_done_count, 1u);
        is_last = (ticket == (unsigned)(gridDim.x - 1));
    }
    __syncthreads();

    // last block finalizes (deterministic order)
    if (is_last) {
        double l = 0.0, m = 0.0;
        for (int i = threadIdx.x; i < (int)gridDim.x; i += NT) {
            float2 v = g_partials[i];
            l += (double)v.x;
            m += (double)v.y;
        }
        #pragma unroll
        for (int off = 16; off > 0; off >>= 1) {
            l += __shfl_xor_sync(0xFFFFFFFFu, l, off);
            m += __shfl_xor_sync(0xFFFFFFFFu, m, off);
        }
        __shared__ double dl[NT / 32];
        __shared__ double dm[NT / 32];
        if (lane == 0) { dl[wid] = l; dm[wid] = m; }
        __syncthreads();
        if (threadIdx.x == 0) {
            double vl = 0.0, vm = 0.0;
            #pragma unroll
            for (int w = 0; w < NT / 32; w++) { vl += dl[w]; vm += dm[w]; }
            out[0] = (float)(vl / (vm + (double)EPS_F));
            g_done_count = 0;   // reset for next graph replay
        }
    }
}

extern "C" void kernel_launch(void* const* d_in, const int* in_sizes, int n_in,
                              void* d_out, int out_size)
{
    const float* pred = (const float*)d_in[0];
    const float* gt   = (const float*)d_in[1];
    float* out = (float*)d_out;

    int total = in_sizes[0] / 7;

    gwd_fused<<<NB1, NT>>>(pred, gt, out, total);
}

// round 9
// speedup vs baseline: 1.3563x; 1.2388x over previous
#include <cuda_runtime.h>
#include <cuda_bf16.h>
#include <cstdint>

#define EPS_F      1e-8f
#define EPS4_F     4e-8f                 // 4*EPS  (clip on raw squares)
#define EPS16_F    1.6e-7f               // 16*EPS (clip on z product)
#define EPS64_F    6.4e-7f               // 64*EPS (clip on raw det)
#define TAU4_INV   13.333333333333334f   // 4/0.3 (cube-root 1/64 folded in)
#define LOG2E_F    1.4426950408889634f

static constexpr int NT    = 256;
static constexpr int WPB   = NT / 32;    // 8 warps per CTA
static constexpr int NB1   = 1184;       // 148 SMs * 8
static constexpr int WT_F  = 224;        // floats per tensor per warp-tile (32 boxes * 7)
static constexpr int WT_F4 = 56;         // float4 per tensor per warp-tile

__device__ float2       g_partials[NB1];
__device__ unsigned int g_done_count;

__device__ __forceinline__ float warp_sum(float v) {
    #pragma unroll
    for (int off = 16; off > 0; off >>= 1)
        v += __shfl_xor_sync(0xFFFFFFFFu, v, off);
    return v;
}
__device__ __forceinline__ float fsqrt_ap(float x) {
    float r; asm("sqrt.approx.f32 %0, %1;" : "=f"(r) : "f"(x)); return r;
}
__device__ __forceinline__ float ex2_ap(float x) {
    float r; asm("ex2.approx.f32 %0, %1;" : "=f"(r) : "f"(x)); return r;
}
__device__ __forceinline__ float lg2_ap(float x) {
    float r; asm("lg2.approx.f32 %0, %1;" : "=f"(r) : "f"(x)); return r;
}

// per-box loss; covariance factor 0.25 folded out algebraically
__device__ __forceinline__ void box_loss(
    const float* __restrict__ p, const float* __restrict__ g,
    float& lsum, float& msum)
{
    float p0 = p[0], p1 = p[1], p2 = p[2], p3 = p[3], p4v = p[4], p5 = p[5], p6 = p[6];
    float g0 = g[0], g1 = g[1], g2 = g[2], g3 = g[3], g4v = g[4], g5 = g[5], g6 = g[6];

    float dx = p0 - g0, dy = p1 - g1, dz = p2 - g2;
    float mu = fmaf(dx, dx, fmaf(dy, dy, dz * dz));

    float tp = p3 * p3, up = p4v * p4v, vp = p5 * p5;
    float tt = g3 * g3, ut = g4v * g4v, vt = g5 * g5;

    float mtp = fmaxf(tp, EPS4_F);
    float mup = fmaxf(up, EPS4_F);
    float mvp = fmaxf(vp, EPS4_F);

    float cd = __cosf(p6 - g6);
    float cc = cd * cd;
    float ss = 1.0f - cc;
    float t1 = mtp * tt, t2 = mup * ut;
    float t3 = mtp * ut, t4 = mup * tt;
    float trM = fmaf(cc, t1 + t2, ss * (t3 + t4));
    float trS = fsqrt_ap(fmaf(2.0f, fsqrt_ap(t1 * t2), trM));   // sqrt(l1)+sqrt(l2)

    float sz = fsqrt_ap(fmaxf(mvp * vt, EPS16_F));

    float traces = (tp + up + vp) + (tt + ut + vt);
    float w2 = fmaf(0.25f, traces - 2.0f * (trS + sz), mu);

    float detr = fmaxf(tt * ut * vt, EPS64_F);
    float invd = ex2_ap(lg2_ap(detr) * (-1.0f / 3.0f)) * TAU4_INV;

    float loss = 1.0f - ex2_ap(-w2 * invd * LOG2E_F);
    if (g0 != 0.0f) { lsum += loss; msum += 1.0f; }
}

__global__ __launch_bounds__(NT) void gwd_fused(
    const float* __restrict__ pred,
    const float* __restrict__ gt,
    float* __restrict__ out,
    int total)
{
    // warp-private staging slots (no cross-warp sharing -> no block barriers)
    __shared__ __align__(16) float swp[WPB][WT_F];
    __shared__ __align__(16) float swg[WPB][WT_F];

    const int lane = threadIdx.x & 31;
    const int wid  = threadIdx.x >> 5;

    const float4* __restrict__ p4 = (const float4*)pred;
    const float4* __restrict__ g4 = (const float4*)gt;

    const int nwt     = total >> 5;                  // full 32-box warp-tiles
    const int wstride = gridDim.x * WPB;
    const int wt0     = blockIdx.x * WPB + wid;
    const bool lo24   = (lane < WT_F4 - 32);         // lanes 0..23 carry the 2nd float4

    float lsum = 0.0f;
    float msum = 0.0f;

    float4 ra0, ra1, rc0, rc1;
    if (wt0 < nwt) {
        const long long base = 56ll * wt0;
        ra0 = p4[base + lane];  if (lo24) ra1 = p4[base + 32 + lane];
        rc0 = g4[base + lane];  if (lo24) rc1 = g4[base + 32 + lane];
    }

    float4* sp4 = (float4*)swp[wid];
    float4* sg4 = (float4*)swg[wid];
    const float* pl = swp[wid] + 7 * lane;   // stride-7: gcd(7,32)=1, conflict-free
    const float* gl = swg[wid] + 7 * lane;

    for (int wt = wt0; wt < nwt; wt += wstride) {
        // stage current tile (consumes staging regs)
        sp4[lane] = ra0;  if (lo24) sp4[32 + lane] = ra1;
        sg4[lane] = rc0;  if (lo24) sg4[32 + lane] = rc1;
        __syncwarp();

        // prefetch next tile: LDG latency overlaps LDS+compute below
        const int next = wt + wstride;
        if (next < nwt) {
            const long long base = 56ll * next;
            ra0 = p4[base + lane];  if (lo24) ra1 = p4[base + 32 + lane];
            rc0 = g4[base + lane];  if (lo24) rc1 = g4[base + 32 + lane];
        }

        box_loss(pl, gl, lsum, msum);
        __syncwarp();        // all lanes done reading before next overwrite
    }

    // ragged tail boxes (0 for this shape)
    if (blockIdx.x == 0 && wid == 0) {
        for (int b = (nwt << 5) + lane; b < total; b += 32) {
            const float* p = pred + 7ll * b;
            const float* g = gt   + 7ll * b;
            float pr[7], gr[7];
            #pragma unroll
            for (int k = 0; k < 7; k++) { pr[k] = __ldg(p + k); gr[k] = __ldg(g + k); }
            box_loss(pr, gr, lsum, msum);
        }
    }

    // block reduction
    lsum = warp_sum(lsum);
    msum = warp_sum(msum);

    __shared__ float sl[WPB];
    __shared__ float sm[WPB];
    if (lane == 0) { sl[wid] = lsum; sm[wid] = msum; }
    __syncthreads();

    __shared__ bool is_last;
    if (threadIdx.x == 0) {
        float vl = 0.0f, vm = 0.0f;
        #pragma unroll
        for (int w = 0; w < WPB; w++) { vl += sl[w]; vm += sm[w]; }
        g_partials[blockIdx.x] = make_float2(vl, vm);
        __threadfence();
        unsigned int ticket = atomicAdd(&g_done_count, 1u);
        is_last = (ticket == (unsigned)(gridDim.x - 1));
    }
    __syncthreads();

    // last block finalizes (deterministic order)
    if (is_last) {
        double l = 0.0, m = 0.0;
        for (int i = threadIdx.x; i < (int)gridDim.x; i += NT) {
            float2 v = g_partials[i];
            l += (double)v.x;
            m += (double)v.y;
        }
        #pragma unroll
        for (int off = 16; off > 0; off >>= 1) {
            l += __shfl_xor_sync(0xFFFFFFFFu, l, off);
            m += __shfl_xor_sync(0xFFFFFFFFu, m, off);
        }
        __shared__ double dl[WPB];
        __shared__ double dm[WPB];
        if (lane == 0) { dl[wid] = l; dm[wid] = m; }
        __syncthreads();
        if (threadIdx.x == 0) {
            double vl = 0.0, vm = 0.0;
            #pragma unroll
            for (int w = 0; w < WPB; w++) { vl += dl[w]; vm += dm[w]; }
            out[0] = (float)(vl / (vm + (double)EPS_F));
            g_done_count = 0;   // reset for next graph replay
        }
    }
}

extern "C" void kernel_launch(void* const* d_in, const int* in_sizes, int n_in,
                              void* d_out, int out_size)
{
    const float* pred = (const float*)d_in[0];
    const float* gt   = (const float*)d_in[1];
    float* out = (float*)d_out;

    int total = in_sizes[0] / 7;

    gwd_fused<<<NB1, NT>>>(pred, gt, out, total);
}

// round 10
// speedup vs baseline: 1.5435x; 1.1380x over previous
#include <cuda_runtime.h>
#include <cuda_bf16.h>
#include <cstdint>

#define EPS_F      1e-8f
#define EPS4_F     4e-8f                 // 4*EPS  (clip on raw squares)
#define EPS16_F    1.6e-7f               // 16*EPS (clip on z product)
#define EPS64_F    6.4e-7f               // 64*EPS (clip on raw det)
#define TAU4_INV   13.333333333333334f   // 4/0.3 (cube-root 1/64 folded in)
#define LOG2E_F    1.4426950408889634f

static constexpr int NT    = 256;
static constexpr int WPB   = NT / 32;    // 8 warps per CTA
static constexpr int NB1   = 1036;       // 148 SMs * 7 (smem-limited occupancy)
static constexpr int WT_F  = 224;        // floats per tensor per warp-tile (32 boxes * 7)
static constexpr int WT_F4 = 56;         // float4 per tensor per warp-tile

__device__ float2       g_partials[NB1];
__device__ unsigned int g_done_count;

__device__ __forceinline__ float warp_sum(float v) {
    #pragma unroll
    for (int off = 16; off > 0; off >>= 1)
        v += __shfl_xor_sync(0xFFFFFFFFu, v, off);
    return v;
}
__device__ __forceinline__ float fsqrt_ap(float x) {
    float r; asm("sqrt.approx.f32 %0, %1;" : "=f"(r) : "f"(x)); return r;
}
__device__ __forceinline__ float ex2_ap(float x) {
    float r; asm("ex2.approx.f32 %0, %1;" : "=f"(r) : "f"(x)); return r;
}
__device__ __forceinline__ float lg2_ap(float x) {
    float r; asm("lg2.approx.f32 %0, %1;" : "=f"(r) : "f"(x)); return r;
}
__device__ __forceinline__ uint32_t smem_u32(const void* p) {
    return (uint32_t)__cvta_generic_to_shared(p);
}
// 16B global->shared async copy, L2-only (.cg): streaming, no L1 pollution,
// no destination registers.
__device__ __forceinline__ void cp16(uint32_t dst, const void* src) {
    asm volatile("cp.async.cg.shared.global [%0], [%1], 16;" :: "r"(dst), "l"(src));
}

// per-box loss; covariance factor 0.25 folded out algebraically
__device__ __forceinline__ void box_loss(
    const float* __restrict__ p, const float* __restrict__ g,
    float& lsum, float& msum)
{
    float p0 = p[0], p1 = p[1], p2 = p[2], p3 = p[3], p4v = p[4], p5 = p[5], p6 = p[6];
    float g0 = g[0], g1 = g[1], g2 = g[2], g3 = g[3], g4v = g[4], g5 = g[5], g6 = g[6];

    float dx = p0 - g0, dy = p1 - g1, dz = p2 - g2;
    float mu = fmaf(dx, dx, fmaf(dy, dy, dz * dz));

    float tp = p3 * p3, up = p4v * p4v, vp = p5 * p5;
    float tt = g3 * g3, ut = g4v * g4v, vt = g5 * g5;

    float mtp = fmaxf(tp, EPS4_F);
    float mup = fmaxf(up, EPS4_F);
    float mvp = fmaxf(vp, EPS4_F);

    float cd = __cosf(p6 - g6);
    float cc = cd * cd;
    float ss = 1.0f - cc;
    float t1 = mtp * tt, t2 = mup * ut;
    float t3 = mtp * ut, t4 = mup * tt;
    float trM = fmaf(cc, t1 + t2, ss * (t3 + t4));
    float trS = fsqrt_ap(fmaf(2.0f, fsqrt_ap(t1 * t2), trM));   // sqrt(l1)+sqrt(l2)

    float sz = fsqrt_ap(fmaxf(mvp * vt, EPS16_F));

    float traces = (tp + up + vp) + (tt + ut + vt);
    float w2 = fmaf(0.25f, traces - 2.0f * (trS + sz), mu);

    float detr = fmaxf(tt * ut * vt, EPS64_F);
    float invd = ex2_ap(lg2_ap(detr) * (-1.0f / 3.0f)) * TAU4_INV;

    float loss = 1.0f - ex2_ap(-w2 * invd * LOG2E_F);
    if (g0 != 0.0f) { lsum += loss; msum += 1.0f; }
}

__global__ __launch_bounds__(NT) void gwd_fused(
    const float* __restrict__ pred,
    const float* __restrict__ gt,
    float* __restrict__ out,
    int total)
{
    // per-warp double-buffered staging: [buf][warp][pred|gt][56 float4]
    __shared__ __align__(16) float4 sbuf[2][WPB][2][WT_F4];

    const int lane = threadIdx.x & 31;
    const int wid  = threadIdx.x >> 5;

    const float4* __restrict__ p4 = (const float4*)pred;
    const float4* __restrict__ g4 = (const float4*)gt;

    const int nwt     = total >> 5;                  // full 32-box warp-tiles
    const int wstride = gridDim.x * WPB;
    const int wt0     = blockIdx.x * WPB + wid;
    const bool lo24   = (lane < WT_F4 - 32);         // lanes 0..23 carry a 2nd float4

    float lsum = 0.0f;
    float msum = 0.0f;

    // per-warp tile stage via cp.async (no destination registers)
    auto stage = [&](int buf, int wt) {
        const float4* ps = p4 + 56ll * wt;
        const float4* gs = g4 + 56ll * wt;
        const uint32_t dp = smem_u32(&sbuf[buf][wid][0][0]);
        const uint32_t dg = smem_u32(&sbuf[buf][wid][1][0]);
        cp16(dp + lane * 16u, ps + lane);
        cp16(dg + lane * 16u, gs + lane);
        if (lo24) {
            cp16(dp + (32u + lane) * 16u, ps + 32 + lane);
            cp16(dg + (32u + lane) * 16u, gs + 32 + lane);
        }
    };

    // prologue: stage first tile
    if (wt0 < nwt) stage(0, wt0);
    asm volatile("cp.async.commit_group;");

    int buf = 0;
    for (int wt = wt0; wt < nwt; wt += wstride) {
        // stage next tile into the other buffer (overlaps this tile's compute)
        const int nxt = wt + wstride;
        if (nxt < nwt) stage(buf ^ 1, nxt);
        asm volatile("cp.async.commit_group;");

        // wait for the current tile's group (the just-committed one may stay in flight)
        asm volatile("cp.async.wait_group 1;");
        __syncwarp();

        const float* pl = (const float*)&sbuf[buf][wid][0][0] + 7 * lane;
        const float* gl = (const float*)&sbuf[buf][wid][1][0] + 7 * lane;
        box_loss(pl, gl, lsum, msum);   // stride-7 LDS: gcd(7,32)=1, conflict-free

        __syncwarp();                   // all lanes done reading before overwrite
        buf ^= 1;
    }

    // ragged tail boxes (0 for this shape)
    if (blockIdx.x == 0 && wid == 0) {
        for (int b = (nwt << 5) + lane; b < total; b += 32) {
            const float* p = pred + 7ll * b;
            const float* g = gt   + 7ll * b;
            float pr[7], gr[7];
            #pragma unroll
            for (int k = 0; k < 7; k++) { pr[k] = __ldg(p + k); gr[k] = __ldg(g + k); }
            box_loss(pr, gr, lsum, msum);
        }
    }

    // block reduction
    lsum = warp_sum(lsum);
    msum = warp_sum(msum);

    __shared__ float sl[WPB];
    __shared__ float sm[WPB];
    if (lane == 0) { sl[wid] = lsum; sm[wid] = msum; }
    __syncthreads();

    __shared__ bool is_last;
    if (threadIdx.x == 0) {
        float vl = 0.0f, vm = 0.0f;
        #pragma unroll
        for (int w = 0; w < WPB; w++) { vl += sl[w]; vm += sm[w]; }
        g_partials[blockIdx.x] = make_float2(vl, vm);
        __threadfence();
        unsigned int ticket = atomicAdd(&g_done_count, 1u);
        is_last = (ticket == (unsigned)(gridDim.x - 1));
    }
    __syncthreads();

    // last block finalizes (deterministic order)
    if (is_last) {
        double l = 0.0, m = 0.0;
        for (int i = threadIdx.x; i < (int)gridDim.x; i += NT) {
            float2 v = g_partials[i];
            l += (double)v.x;
            m += (double)v.y;
        }
        #pragma unroll
        for (int off = 16; off > 0; off >>= 1) {
            l += __shfl_xor_sync(0xFFFFFFFFu, l, off);
            m += __shfl_xor_sync(0xFFFFFFFFu, m, off);
        }
        __shared__ double dl[WPB];
        __shared__ double dm[WPB];
        if (lane == 0) { dl[wid] = l; dm[wid] = m; }
        __syncthreads();
        if (threadIdx.x == 0) {
            double vl = 0.0, vm = 0.0;
            #pragma unroll
            for (int w = 0; w < WPB; w++) { vl += dl[w]; vm += dm[w]; }
            out[0] = (float)(vl / (vm + (double)EPS_F));
            g_done_count = 0;   // reset for next graph replay
        }
    }
}

extern "C" void kernel_launch(void* const* d_in, const int* in_sizes, int n_in,
                              void* d_out, int out_size)
{
    const float* pred = (const float*)d_in[0];
    const float* gt   = (const float*)d_in[1];
    float* out = (float*)d_out;

    int total = in_sizes[0] / 7;

    gwd_fused<<<NB1, NT>>>(pred, gt, out, total);
}